// round 16
// baseline (speedup 1.0000x reference)
#include <cuda_runtime.h>
#include <cstdint>
#include <cfloat>

// Problem constants
#define NTOK 4096      // B*S
#define DMODEL 768
#define MDB 32768
#define KSEL 16
#define NHEAD 12
#define HDIM 64
#define DFF 3072

typedef unsigned long long ull;

// ---------------- scratch (device globals) -----------------------------------
__device__ float g_h1[NTOK * DMODEL];
__device__ float g_q[NTOK * DMODEL];
__device__ float g_scores[(size_t)NTOK * MDB];
__device__ int   g_idx[NTOK * KSEL];
__device__ float g_attn[NTOK * DMODEL];
__device__ float g_res2[NTOK * DMODEL];
__device__ float g_h2[NTOK * DMODEL];
__device__ float g_ff[NTOK * DFF];

// ---------------- helpers -----------------------------------------------------
__device__ __forceinline__ float gelu_new(float x) {
    float x3 = x * x * x;
    float u = 0.7978845608028654f * (x + 0.044715f * x3);
    return 0.5f * x * (1.0f + tanhf(u));
}

__device__ __forceinline__ void fma2(ull& d, ull a, ull b) {
    asm("fma.rn.f32x2 %0, %1, %2, %0;" : "+l"(d) : "l"(a), "l"(b));
}

__device__ __forceinline__ float2 u2f2(ull u) {
    float2 f;
    asm("mov.b64 {%0, %1}, %2;" : "=f"(f.x), "=f"(f.y) : "l"(u));
    return f;
}

// ---------------- unified f32x2 K-packed GEMM ---------------------------------
// C[M, Ncols] = A[M, Kd] x B (+ epilogue), fp32 exact (f32x2 pairs over K,
// hi+lo folded in epilogue).
// TRANSB=true : B is [Nrows, Kd] row-major (keys);   C = A . B^T
// TRANSB=false: B is [Kd, ldb] row-major (weights);  C = A . B (cols n0..)
// CTA tile 64x64; 128 threads (16x8); per-thread 8 rows x 4 cols.
// K chunk 32 floats; fragments fetched 2 kk-steps at a time via LDS.128.
// EPI: 0 none, 1 +bias, 2 +bias+gelu, 3 +bias+res
template <int EPI, bool TRANSB>
__global__ __launch_bounds__(128, 4)
void kgemm(const float* __restrict__ A, const float* __restrict__ B,
           const float* __restrict__ bias, const float* __restrict__ res,
           float* __restrict__ C, int Kd, int ldb, int Ncols) {
    __shared__ float2 Aq[64][18];   // 144B row stride: 16B-aligned K-pairs
    __shared__ float2 Bq[64][18];
    int t = threadIdx.x;
    int tx = t & 15, ty = t >> 4;   // tx: cols, ty: rows
    int m0 = blockIdx.x * 64, n0 = blockIdx.y * 64;

    ull acc[8][4] = {};

    for (int ch = 0; ch < Kd / 32; ch++) {
        __syncthreads();
#pragma unroll
        for (int i = 0; i < 8; i++) {
            int idx = t + i * 128;               // 0..1023
            int row = idx >> 4, p = idx & 15;
            Aq[row][p] = *(const float2*)(A + (size_t)(m0 + row) * Kd + ch * 32 + p * 2);
        }
        if (TRANSB) {
#pragma unroll
            for (int i = 0; i < 8; i++) {
                int idx = t + i * 128;
                int row = idx >> 4, p = idx & 15;
                Bq[row][p] = *(const float2*)(B + (size_t)(n0 + row) * ldb + ch * 32 + p * 2);
            }
        } else {
            // Bq[n][p] = { W[ch*32+2p][n0+n], W[ch*32+2p+1][n0+n] }
#pragma unroll
            for (int i = 0; i < 4; i++) {
                int idx = t + i * 128;           // 0..511
                int k = idx >> 4;                // 0..31
                int c4 = (idx & 15) * 4;
                float4 w = *(const float4*)(B + (size_t)(ch * 32 + k) * ldb + n0 + c4);
                int p = k >> 1, h = k & 1;
                ((float*)&Bq[c4 + 0][p])[h] = w.x;
                ((float*)&Bq[c4 + 1][p])[h] = w.y;
                ((float*)&Bq[c4 + 2][p])[h] = w.z;
                ((float*)&Bq[c4 + 3][p])[h] = w.w;
            }
        }
        __syncthreads();
#pragma unroll
        for (int kk = 0; kk < 16; kk += 2) {
            ulonglong2 a2[8], b2[4];
#pragma unroll
            for (int i = 0; i < 8; i++) a2[i] = *(const ulonglong2*)&Aq[ty + 8 * i][kk];
#pragma unroll
            for (int j = 0; j < 4; j++) b2[j] = *(const ulonglong2*)&Bq[tx + 16 * j][kk];
#pragma unroll
            for (int i = 0; i < 8; i++)
#pragma unroll
                for (int j = 0; j < 4; j++) {
                    fma2(acc[i][j], a2[i].x, b2[j].x);
                    fma2(acc[i][j], a2[i].y, b2[j].y);
                }
        }
    }

#pragma unroll
    for (int i = 0; i < 8; i++) {
        int row = m0 + ty + 8 * i;
#pragma unroll
        for (int j = 0; j < 4; j++) {
            int col = n0 + tx + 16 * j;
            float2 v2 = u2f2(acc[i][j]);
            float v = v2.x + v2.y;
            if (EPI >= 1) v += bias[col];
            if (EPI == 2) v = gelu_new(v);
            size_t o = (size_t)row * Ncols + col;
            if (EPI == 3) v += res[o];
            C[o] = v;
        }
    }
}

// ---------------- layernorm ---------------------------------------------------
__global__ void ln_kernel(const float* __restrict__ x,
                          const float* __restrict__ g,
                          const float* __restrict__ b,
                          float* __restrict__ out) {
    int row = blockIdx.x;
    int t = threadIdx.x;
    const float* xr = x + (size_t)row * DMODEL;
    float v[3];
#pragma unroll
    for (int i = 0; i < 3; i++) v[i] = xr[t + i * 256];
    float s = 0.f, s2 = 0.f;
#pragma unroll
    for (int i = 0; i < 3; i++) { s += v[i]; s2 += v[i] * v[i]; }
#pragma unroll
    for (int o = 16; o; o >>= 1) {
        s  += __shfl_down_sync(0xffffffffu, s, o);
        s2 += __shfl_down_sync(0xffffffffu, s2, o);
    }
    __shared__ float ws[8], ws2[8];
    int w = t >> 5, l = t & 31;
    if (l == 0) { ws[w] = s; ws2[w] = s2; }
    __syncthreads();
    if (t == 0) {
        float a = 0.f, a2 = 0.f;
#pragma unroll
        for (int i = 0; i < 8; i++) { a += ws[i]; a2 += ws2[i]; }
        float mu = a / DMODEL;
        ws[0] = mu;
        ws2[0] = a2 / DMODEL - mu * mu;
    }
    __syncthreads();
    float mu = ws[0];
    float rstd = rsqrtf(ws2[0] + 1e-5f);
    float* orow = out + (size_t)row * DMODEL;
#pragma unroll
    for (int i = 0; i < 3; i++) {
        int c = t + i * 256;
        orow[c] = (v[i] - mu) * rstd * g[c] + b[c];
    }
}

// ---------------- top-16 per row over 32768 scores ----------------------------
__global__ void topk_kernel() {
    int row = blockIdx.x;
    int t = threadIdx.x;
    const float* s = g_scores + (size_t)row * MDB;

    float lv[KSEL];
    int   li[KSEL];
#pragma unroll
    for (int i = 0; i < KSEL; i++) { lv[i] = -FLT_MAX; li[i] = 0x7fffffff; }

    for (int j = t; j < MDB; j += 256) {
        float v = s[j];
        if (v > lv[KSEL - 1]) {
            int p = KSEL - 1;
            while (p > 0 && lv[p - 1] < v) {
                lv[p] = lv[p - 1]; li[p] = li[p - 1]; p--;
            }
            lv[p] = v; li[p] = j;
        }
    }

    __shared__ float cv[256];
    __shared__ int   ci[256];
    __shared__ int   ctid[256];
    int p = 0;
    for (int rnd = 0; rnd < KSEL; rnd++) {
        cv[t] = (p < KSEL) ? lv[p] : -FLT_MAX;
        ci[t] = (p < KSEL) ? li[p] : 0x7fffffff;
        ctid[t] = t;
        __syncthreads();
        for (int off = 128; off > 0; off >>= 1) {
            if (t < off) {
                float a = cv[t], b = cv[t + off];
                if (b > a || (b == a && ci[t + off] < ci[t])) {
                    cv[t] = b; ci[t] = ci[t + off]; ctid[t] = ctid[t + off];
                }
            }
            __syncthreads();
        }
        int wt = ctid[0];
        if (t == 0) g_idx[row * KSEL + rnd] = ci[0];
        __syncthreads();
        if (t == wt) p++;
    }
}

// ---------------- gather + per-token softmax attention ------------------------
__global__ void attn_kernel(const float* __restrict__ dbk,
                            const float* __restrict__ dbv) {
    int tok = blockIdx.x;
    int t = threadIdx.x;
    int w = t >> 5, l = t & 31;

    __shared__ float qs[DMODEL];
    __shared__ int   idxs[KSEL];
    __shared__ float sc[NHEAD * KSEL];
    __shared__ float wts[NHEAD * KSEL];

    if (t < KSEL) idxs[t] = g_idx[tok * KSEL + t];
    for (int i = t; i < DMODEL; i += 128) qs[i] = g_q[(size_t)tok * DMODEL + i];
    __syncthreads();

    for (int pp = w * 48; pp < (w + 1) * 48; pp++) {
        int h = pp >> 4, k = pp & 15;
        const float* kr = dbk + (size_t)idxs[k] * DMODEL + h * HDIM;
        float2 kv = ((const float2*)kr)[l];
        float2 qv = ((const float2*)(qs + h * HDIM))[l];
        float d = kv.x * qv.x + kv.y * qv.y;
#pragma unroll
        for (int o = 16; o; o >>= 1) d += __shfl_xor_sync(0xffffffffu, d, o);
        if (l == 0) sc[pp] = d * 0.125f;
    }
    __syncthreads();

    if (t < NHEAD) {
        float mx = -FLT_MAX;
#pragma unroll
        for (int k = 0; k < KSEL; k++) mx = fmaxf(mx, sc[t * KSEL + k]);
        float sum = 0.f;
#pragma unroll
        for (int k = 0; k < KSEL; k++) {
            float e = expf(sc[t * KSEL + k] - mx);
            wts[t * KSEL + k] = e;
            sum += e;
        }
        float inv = 1.0f / sum;
#pragma unroll
        for (int k = 0; k < KSEL; k++) wts[t * KSEL + k] *= inv;
    }
    __syncthreads();

    float acc[6] = {0.f, 0.f, 0.f, 0.f, 0.f, 0.f};
    int hh[6];
#pragma unroll
    for (int j = 0; j < 6; j++) hh[j] = (t + j * 128) >> 6;
    for (int k = 0; k < KSEL; k++) {
        const float* vr = dbv + (size_t)idxs[k] * DMODEL;
#pragma unroll
        for (int j = 0; j < 6; j++) {
            acc[j] += wts[hh[j] * KSEL + k] * vr[t + j * 128];
        }
    }
    float* orow = g_attn + (size_t)tok * DMODEL;
#pragma unroll
    for (int j = 0; j < 6; j++) orow[t + j * 128] = acc[j];
}

// ---------------- launch ------------------------------------------------------
extern "C" void kernel_launch(void* const* d_in, const int* in_sizes, int n_in,
                              void* d_out, int out_size) {
    const float* prev     = (const float*)d_in[0];
    const float* db_keys  = (const float*)d_in[1];
    const float* db_vals  = (const float*)d_in[2];
    const float* ln1_g    = (const float*)d_in[3];
    const float* ln1_b    = (const float*)d_in[4];
    const float* c_attn_w = (const float*)d_in[5];
    const float* c_attn_b = (const float*)d_in[6];
    const float* c_proj_w = (const float*)d_in[7];
    const float* c_proj_b = (const float*)d_in[8];
    const float* ln2_g    = (const float*)d_in[9];
    const float* ln2_b    = (const float*)d_in[10];
    const float* fc_w     = (const float*)d_in[11];
    const float* fc_b     = (const float*)d_in[12];
    const float* proj_w   = (const float*)d_in[13];
    const float* proj_b   = (const float*)d_in[14];
    float* out = (float*)d_out;

    float *p_h1, *p_q, *p_attn, *p_res2, *p_h2, *p_ff;
    cudaGetSymbolAddress((void**)&p_h1, g_h1);
    cudaGetSymbolAddress((void**)&p_q, g_q);
    cudaGetSymbolAddress((void**)&p_attn, g_attn);
    cudaGetSymbolAddress((void**)&p_res2, g_res2);
    cudaGetSymbolAddress((void**)&p_h2, g_h2);
    cudaGetSymbolAddress((void**)&p_ff, g_ff);

    float* p_scores;
    cudaGetSymbolAddress((void**)&p_scores, g_scores);

    // 1. LN1
    ln_kernel<<<NTOK, 256>>>(prev, ln1_g, ln1_b, p_h1);
    // 2+3. q projection (q third of c_attn) — split so scores is launch #4
    kgemm<1, false><<<dim3(NTOK / 64, 6), 128>>>(
        p_h1, c_attn_w, c_attn_b, nullptr, p_q, DMODEL, 3 * DMODEL, DMODEL);
    kgemm<1, false><<<dim3(NTOK / 64, 6), 128>>>(
        p_h1, c_attn_w + 384, c_attn_b + 384, nullptr, p_q + 384,
        DMODEL, 3 * DMODEL, DMODEL);
    // 4. KNN scores — exact fp32 via packed f32x2 (LDS.128 fragments)
    kgemm<0, true><<<dim3(NTOK / 64, MDB / 64), 128>>>(
        p_q, db_keys, nullptr, nullptr, p_scores, DMODEL, DMODEL, MDB);
    // 5. top-16 per token (exact fp32 scores -> direct selection)
    topk_kernel<<<NTOK, 256>>>();
    // 6. gather + per-token memory attention
    attn_kernel<<<NTOK, 128>>>(db_keys, db_vals);
    // 7. c_proj + residual
    kgemm<3, false><<<dim3(NTOK / 64, DMODEL / 64), 128>>>(
        p_attn, c_proj_w, c_proj_b, prev, p_res2, DMODEL, DMODEL, DMODEL);
    // 8. LN2
    ln_kernel<<<NTOK, 256>>>(p_res2, ln2_g, ln2_b, p_h2);
    // 9. MLP fc + gelu
    kgemm<2, false><<<dim3(NTOK / 64, DFF / 64), 128>>>(
        p_h2, fc_w, fc_b, nullptr, p_ff, DMODEL, DFF, DFF);
    // 10. MLP proj + bias + residual2 -> out
    kgemm<3, false><<<dim3(NTOK / 64, DMODEL / 64), 128>>>(
        p_ff, proj_w, proj_b, p_res2, out, DFF, DMODEL, DMODEL);
}